// round 2
// baseline (speedup 1.0000x reference)
#include <cuda_runtime.h>
#include <math.h>
#include <stdint.h>

#define BB 32
#define TT 512
#define EE 256
#define UU 512
#define U3 1536
#define NBLK 64          // blocks per direction in recurrence
#define RGRID (2*NBLK)   // total recurrence blocks

// ---------------- device scratch (static; no runtime allocation) ------------
__device__ float    g_xproj[2][BB][TT][U3];   // ~201 MB: x@W + b_in per direction
__device__ float    g_h[2][2][BB][UU];        // [dir][buf][b][u] double-buffered state
__device__ unsigned g_cnt[2][TT];             // per-step barrier counters (memset to 0 each launch)

// ---------------- packed f32x2 helpers (PTX-only FFMA2 on sm_103a) ----------
__device__ __forceinline__ unsigned long long ffma2(unsigned long long a,
                                                    unsigned long long b,
                                                    unsigned long long c) {
    unsigned long long d;
    asm("fma.rn.f32x2 %0, %1, %2, %3;" : "=l"(d) : "l"(a), "l"(b), "l"(c));
    return d;
}
__device__ __forceinline__ unsigned long long dup2(float x) {
    unsigned long long d;
    asm("mov.b64 %0, {%1, %1};" : "=l"(d) : "f"(x));
    return d;
}
__device__ __forceinline__ float2 unpack2(unsigned long long v) {
    float2 r;
    asm("mov.b64 {%0, %1}, %2;" : "=f"(r.x), "=f"(r.y) : "l"(v));
    return r;
}

// ---------------- Kernel A: x_proj = emb[tokens] @ W + b_in -----------------
#define BM 128
#define BN 64
#define BK 16

__global__ void __launch_bounds__(256) xproj_kernel(
    const int* __restrict__ tokens,
    const float* __restrict__ emb,
    const float* __restrict__ W_fw, const float* __restrict__ b_in_fw,
    const float* __restrict__ W_bw, const float* __restrict__ b_in_bw)
{
    __shared__ __align__(16) float As[BK][BM];
    __shared__ __align__(16) float Bs[BK][BN];
    __shared__ int toks[BM];

    const int d  = blockIdx.z;
    const float* __restrict__ Wp = d ? W_bw : W_fw;
    const float* __restrict__ bp = d ? b_in_bw : b_in_fw;
    const int n0 = blockIdx.x * BN;
    const int m0 = blockIdx.y * BM;
    const int tid = threadIdx.x;
    const int tx = tid & 15;       // 16 col-threads * 4 cols
    const int ty = tid >> 4;       // 16 row-threads * 8 rows

    if (tid < BM) toks[tid] = tokens[m0 + tid];
    __syncthreads();

    unsigned long long acc[4][4];  // [m-pair][n], packed over m
#pragma unroll
    for (int i = 0; i < 4; i++)
#pragma unroll
        for (int j = 0; j < 4; j++) acc[i][j] = 0ull;

    for (int k0 = 0; k0 < EE; k0 += BK) {
        // A tile: gathered embedding rows, stored transposed As[k][m]
#pragma unroll
        for (int i = 0; i < 2; i++) {
            int id = tid * 2 + i;          // 0..511 float4 slots
            int m  = id >> 2;
            int kg = id & 3;
            float4 v = *(const float4*)(emb + (size_t)toks[m] * EE + k0 + kg * 4);
            As[kg*4+0][m] = v.x; As[kg*4+1][m] = v.y;
            As[kg*4+2][m] = v.z; As[kg*4+3][m] = v.w;
        }
        // B tile: W[k][n]
        {
            int k = tid >> 4, ng = tid & 15;
            *(float4*)&Bs[k][ng*4] =
                *(const float4*)(Wp + (size_t)(k0 + k) * U3 + n0 + ng * 4);
        }
        __syncthreads();
#pragma unroll
        for (int k = 0; k < BK; k++) {
            ulonglong2 a01 = *(const ulonglong2*)&As[k][ty*8];
            ulonglong2 a23 = *(const ulonglong2*)&As[k][ty*8+4];
            float4 b4 = *(const float4*)&Bs[k][tx*4];
            unsigned long long ap[4] = {a01.x, a01.y, a23.x, a23.y};
            unsigned long long bp2[4] = {dup2(b4.x), dup2(b4.y), dup2(b4.z), dup2(b4.w)};
#pragma unroll
            for (int i = 0; i < 4; i++)
#pragma unroll
                for (int j = 0; j < 4; j++)
                    acc[i][j] = ffma2(ap[i], bp2[j], acc[i][j]);
        }
        __syncthreads();
    }

    // store with bias (unpack m-pairs)
    float4 bias = *(const float4*)(bp + n0 + tx * 4);
    float* gx = &g_xproj[0][0][0][0];
#pragma unroll
    for (int i = 0; i < 4; i++) {
        float2 c0 = unpack2(acc[i][0]);
        float2 c1 = unpack2(acc[i][1]);
        float2 c2 = unpack2(acc[i][2]);
        float2 c3 = unpack2(acc[i][3]);
        size_t mlo = (size_t)(m0 + ty * 8 + i * 2);
        float4 vlo = { c0.x + bias.x, c1.x + bias.y, c2.x + bias.z, c3.x + bias.w };
        float4 vhi = { c0.y + bias.x, c1.y + bias.y, c2.y + bias.z, c3.y + bias.w };
        *(float4*)(gx + ((size_t)d * (BB*TT) + mlo)     * U3 + n0 + tx * 4) = vlo;
        *(float4*)(gx + ((size_t)d * (BB*TT) + mlo + 1) * U3 + n0 + tx * 4) = vhi;
    }
}

// ---------------- Kernel B: persistent GRU recurrence -----------------------
// 128 blocks (64 per direction), 256 threads; block owns 8 hidden units.
// Warp layout: 8 batches x 4 units -> h load is 1 LDS wavefront (swizzled),
// U loads 1 wavefront per gate. Packed f32x2 FMAs along k.
// SMEM: h [32][128] float4 (64KB, swizzled) + U [3][128][8] float4 (48KB) + hout (1KB)
#define SMEM_BYTES (32*128*16 + 3*128*8*16 + 32*8*4)

__global__ void __launch_bounds__(256, 1) gru_kernel(
    const int* __restrict__ tokens,
    const float* __restrict__ U_fw, const float* __restrict__ b_rec_fw,
    const float* __restrict__ U_bw, const float* __restrict__ b_rec_bw,
    float* __restrict__ out)
{
    extern __shared__ float smem[];
    float4* hs4  = (float4*)smem;                  // [32][128] swizzled: [b][kk ^ (b&7)]
    float4* Us4  = hs4 + 32*128;                   // [3][128][8]: (g*128+kk)*8 + ulocal
    float*  hout = (float*)(Us4 + 3*128*8);        // [32][8]

    const int bid = blockIdx.x;
    const int d   = bid >> 6;
    const int jb  = bid & (NBLK - 1);
    const int u0  = jb * 8;
    const int tid = threadIdx.x;
    const int wid = tid >> 5;
    const int lane = tid & 31;
    const int b   = ((wid & 3) << 3) + (lane >> 2);     // batch 0..31
    const int ul  = ((wid >> 2) << 2) + (lane & 3);     // local unit 0..7
    const int u   = u0 + ul;
    const int swz = b & 7;

    const float* __restrict__ Uw = d ? U_bw : U_fw;
    const float* __restrict__ br = d ? b_rec_bw : b_rec_fw;

    // stage this block's 24 U-columns into SMEM once (k packed into float4)
    for (int idx = tid; idx < 3 * 128 * 8; idx += 256) {
        int g  = idx >> 10;          // /(128*8)
        int kk = (idx >> 3) & 127;
        int uu = idx & 7;
        const float* col = Uw + g * 512 + u0 + uu;
        float4 v;
        v.x = col[(size_t)(4*kk + 0) * U3];
        v.y = col[(size_t)(4*kk + 1) * U3];
        v.z = col[(size_t)(4*kk + 2) * U3];
        v.w = col[(size_t)(4*kk + 3) * U3];
        Us4[idx] = v;
    }

    const float brz = br[0*512 + u];
    const float brr = br[1*512 + u];
    const float brh = br[2*512 + u];

    const float* gx = &g_xproj[0][0][0][0];
    const float4* uzp = Us4 + 0*1024 + ul;
    const float4* urp = Us4 + 1*1024 + ul;
    const float4* uhp = Us4 + 2*1024 + ul;
    const float4* hbp = hs4 + b * 128;

    __syncthreads();

    for (int ts = 0; ts < TT; ts++) {
        const int t   = d ? (TT - 1 - ts) : ts;
        const int buf = ts & 1;

        // stage h_prev into swizzled SMEM
        const float4* hp_g = (const float4*)&g_h[d][buf][0][0];
#pragma unroll
        for (int i = 0; i < 16; i++) {
            int id = tid + i * 256;        // 0..4095
            int bb = id >> 7;
            int kk = id & 127;
            hs4[bb * 128 + (kk ^ (bb & 7))] = hp_g[id];
        }
        // early global loads (latency hidden behind sync + dot loop)
        size_t xb = ((size_t)d * (BB*TT) + (size_t)b * TT + t) * U3;
        float xz = gx[xb + u];
        float xr = gx[xb + 512 + u];
        float xh = gx[xb + 1024 + u];
        int   mt = (tokens[b * TT + t] != 0);
        __syncthreads();

        // 512-wide dot products for gates z, r, h (packed f32x2 over k)
        unsigned long long az = 0ull, ar = 0ull, ah = 0ull;
#pragma unroll 4
        for (int kk = 0; kk < 128; kk++) {
            ulonglong2 h2 = *(const ulonglong2*)(hbp + (kk ^ swz));
            ulonglong2 z2 = *(const ulonglong2*)(uzp + kk * 8);
            ulonglong2 r2 = *(const ulonglong2*)(urp + kk * 8);
            ulonglong2 c2 = *(const ulonglong2*)(uhp + kk * 8);
            az = ffma2(h2.x, z2.x, az); az = ffma2(h2.y, z2.y, az);
            ar = ffma2(h2.x, r2.x, ar); ar = ffma2(h2.y, r2.y, ar);
            ah = ffma2(h2.x, c2.x, ah); ah = ffma2(h2.y, c2.y, ah);
        }
        float2 azf = unpack2(az);
        float2 arf = unpack2(ar);
        float2 ahf = unpack2(ah);
        float hz = azf.x + azf.y + brz;
        float hr = arf.x + arf.y + brr;
        float hh = ahf.x + ahf.y + brh;

        float z    = 1.f / (1.f + expf(-(xz + hz)));
        float r    = 1.f / (1.f + expf(-(xr + hr)));
        float cand = tanhf(xh + r * hh);
        float hp   = ((const float*)&hbp[(u >> 2) ^ swz])[u & 3];
        float hn   = z * hp + (1.f - z) * cand;
        if (!mt) hn = hp;

        hout[b * 8 + ul] = hn;
        __syncthreads();

        // coalesced writes: 32 rows x 8 floats -> state buffer + output slice
        if (tid < 64) {
            float4 v  = ((const float4*)hout)[tid];
            int row   = tid >> 1;
            int half  = tid & 1;
            *(float4*)&g_h[d][buf ^ 1][row][u0 + half * 4] = v;
            *(float4*)&out[((size_t)row * TT + t) * (2*UU) + (size_t)d * UU + u0 + half * 4] = v;
        }

        // inter-block barrier (per direction, per step); counters pre-zeroed
        if (ts + 1 < TT) {
            __syncthreads();
            if (tid == 0) {
                __threadfence();
                atomicAdd(&g_cnt[d][ts], 1u);
                volatile unsigned* c = &g_cnt[d][ts];
                while (*c < NBLK) { }
                __threadfence();
            }
            __syncthreads();
        }
    }
}

// ---------------- launch ----------------------------------------------------
extern "C" void kernel_launch(void* const* d_in, const int* in_sizes, int n_in,
                              void* d_out, int out_size)
{
    const int*   tokens   = (const int*)  d_in[0];
    const float* emb      = (const float*)d_in[1];
    const float* W_fw     = (const float*)d_in[2];
    const float* U_fw     = (const float*)d_in[3];
    const float* b_in_fw  = (const float*)d_in[4];
    const float* b_rec_fw = (const float*)d_in[5];
    const float* W_bw     = (const float*)d_in[6];
    const float* U_bw     = (const float*)d_in[7];
    const float* b_in_bw  = (const float*)d_in[8];
    const float* b_rec_bw = (const float*)d_in[9];
    float* out = (float*)d_out;

    void* p;
    cudaGetSymbolAddress(&p, g_h);
    cudaMemsetAsync(p, 0, sizeof(g_h));
    cudaGetSymbolAddress(&p, g_cnt);
    cudaMemsetAsync(p, 0, sizeof(g_cnt));

    dim3 gA(U3 / BN, (BB * TT) / BM, 2);
    xproj_kernel<<<gA, 256>>>(tokens, emb, W_fw, b_in_fw, W_bw, b_in_bw);

    cudaFuncSetAttribute(gru_kernel,
                         cudaFuncAttributeMaxDynamicSharedMemorySize, SMEM_BYTES);
    gru_kernel<<<RGRID, 256, SMEM_BYTES>>>(tokens, U_fw, b_rec_fw,
                                           U_bw, b_rec_bw, out);
}

// round 3
// speedup vs baseline: 1.0144x; 1.0144x over previous
#include <cuda_runtime.h>
#include <math.h>
#include <stdint.h>

#define BB 32
#define TT 512
#define EE 256
#define UU 512
#define U3 1536
#define NBLK 64          // blocks per direction in recurrence
#define RGRID (2*NBLK)   // total recurrence blocks

// ---------------- device scratch (static; no runtime allocation) ------------
__device__ float    g_xproj[2][BB][TT][U3];   // ~201 MB: x@W + b_in per direction
__device__ float    g_h[2][2][BB][UU];        // [dir][buf][b][u] double-buffered state
__device__ unsigned g_cnt[2][TT];             // per-step barrier counters (memset to 0 each launch)

// ---------------- packed f32x2 helpers (PTX-only FFMA2 on sm_103a) ----------
__device__ __forceinline__ unsigned long long ffma2(unsigned long long a,
                                                    unsigned long long b,
                                                    unsigned long long c) {
    unsigned long long d;
    asm("fma.rn.f32x2 %0, %1, %2, %3;" : "=l"(d) : "l"(a), "l"(b), "l"(c));
    return d;
}
__device__ __forceinline__ unsigned long long dup2(float x) {
    unsigned long long d;
    asm("mov.b64 %0, {%1, %1};" : "=l"(d) : "f"(x));
    return d;
}
__device__ __forceinline__ float2 unpack2(unsigned long long v) {
    float2 r;
    asm("mov.b64 {%0, %1}, %2;" : "=f"(r.x), "=f"(r.y) : "l"(v));
    return r;
}

// ---------------- Kernel A: x_proj = emb[tokens] @ W + b_in -----------------
#define BM 128
#define BN 64
#define BK 16

__global__ void __launch_bounds__(256) xproj_kernel(
    const int* __restrict__ tokens,
    const float* __restrict__ emb,
    const float* __restrict__ W_fw, const float* __restrict__ b_in_fw,
    const float* __restrict__ W_bw, const float* __restrict__ b_in_bw)
{
    __shared__ __align__(16) float As[BK][BM];
    __shared__ __align__(16) float Bs[BK][BN];
    __shared__ int toks[BM];

    const int d  = blockIdx.z;
    const float* __restrict__ Wp = d ? W_bw : W_fw;
    const float* __restrict__ bp = d ? b_in_bw : b_in_fw;
    const int n0 = blockIdx.x * BN;
    const int m0 = blockIdx.y * BM;
    const int tid = threadIdx.x;
    const int tx = tid & 15;       // 16 col-threads * 4 cols
    const int ty = tid >> 4;       // 16 row-threads * 8 rows

    if (tid < BM) toks[tid] = tokens[m0 + tid];
    __syncthreads();

    unsigned long long acc[4][4];  // [m-pair][n], packed over m
#pragma unroll
    for (int i = 0; i < 4; i++)
#pragma unroll
        for (int j = 0; j < 4; j++) acc[i][j] = 0ull;

    for (int k0 = 0; k0 < EE; k0 += BK) {
        // A tile: gathered embedding rows, stored transposed As[k][m]
#pragma unroll
        for (int i = 0; i < 2; i++) {
            int id = tid * 2 + i;          // 0..511 float4 slots
            int m  = id >> 2;
            int kg = id & 3;
            float4 v = *(const float4*)(emb + (size_t)toks[m] * EE + k0 + kg * 4);
            As[kg*4+0][m] = v.x; As[kg*4+1][m] = v.y;
            As[kg*4+2][m] = v.z; As[kg*4+3][m] = v.w;
        }
        // B tile: W[k][n]
        {
            int k = tid >> 4, ng = tid & 15;
            *(float4*)&Bs[k][ng*4] =
                *(const float4*)(Wp + (size_t)(k0 + k) * U3 + n0 + ng * 4);
        }
        __syncthreads();
#pragma unroll
        for (int k = 0; k < BK; k++) {
            ulonglong2 a01 = *(const ulonglong2*)&As[k][ty*8];
            ulonglong2 a23 = *(const ulonglong2*)&As[k][ty*8+4];
            float4 b4 = *(const float4*)&Bs[k][tx*4];
            unsigned long long ap[4] = {a01.x, a01.y, a23.x, a23.y};
            unsigned long long bp2[4] = {dup2(b4.x), dup2(b4.y), dup2(b4.z), dup2(b4.w)};
#pragma unroll
            for (int i = 0; i < 4; i++)
#pragma unroll
                for (int j = 0; j < 4; j++)
                    acc[i][j] = ffma2(ap[i], bp2[j], acc[i][j]);
        }
        __syncthreads();
    }

    // store with bias (unpack m-pairs)
    float4 bias = *(const float4*)(bp + n0 + tx * 4);
    float* gx = &g_xproj[0][0][0][0];
#pragma unroll
    for (int i = 0; i < 4; i++) {
        float2 c0 = unpack2(acc[i][0]);
        float2 c1 = unpack2(acc[i][1]);
        float2 c2 = unpack2(acc[i][2]);
        float2 c3 = unpack2(acc[i][3]);
        size_t mlo = (size_t)(m0 + ty * 8 + i * 2);
        float4 vlo = { c0.x + bias.x, c1.x + bias.y, c2.x + bias.z, c3.x + bias.w };
        float4 vhi = { c0.y + bias.x, c1.y + bias.y, c2.y + bias.z, c3.y + bias.w };
        *(float4*)(gx + ((size_t)d * (BB*TT) + mlo)     * U3 + n0 + tx * 4) = vlo;
        *(float4*)(gx + ((size_t)d * (BB*TT) + mlo + 1) * U3 + n0 + tx * 4) = vhi;
    }
}

// ---------------- Kernel B: persistent GRU recurrence -----------------------
// 128 blocks (64/dir), 512 threads, block owns 8 hidden units.
// Warps split K: warps 0-7 -> k[0,256), warps 8-15 -> k[256,512).
// Within a k-half: warp = 8 batches x 4 units (h load = 1 swizzled wavefront).
// f32x2 FMAs, 6 accumulator chains. SMEM reduction combines the two k-halves.
// SMEM: h [32][128]f4 (64KB) + U [3][128][8]f4 (48KB) + red [32][8]f4 (4KB) + hout (1KB)
#define SMEM_BYTES (32*128*16 + 3*128*8*16 + 32*8*16 + 32*8*4)

__global__ void __launch_bounds__(512, 1) gru_kernel(
    const int* __restrict__ tokens,
    const float* __restrict__ U_fw, const float* __restrict__ b_rec_fw,
    const float* __restrict__ U_bw, const float* __restrict__ b_rec_bw,
    float* __restrict__ out)
{
    extern __shared__ float smem[];
    float4* hs4  = (float4*)smem;                  // [32][128] swizzled: [b][kk ^ (b&7)]
    float4* Us4  = hs4 + 32*128;                   // [3][128][8]: (g*128+kk)*8 + ulocal
    float4* red  = Us4 + 3*128*8;                  // [32][8] partial (hz,hr,hh,-)
    float*  hout = (float*)(red + 32*8);           // [32][8]

    const int bid = blockIdx.x;
    const int d   = bid >> 6;
    const int jb  = bid & (NBLK - 1);
    const int u0  = jb * 8;
    const int tid = threadIdx.x;
    const int wid = tid >> 5;
    const int lane = tid & 31;
    const int khalf = wid >> 3;                       // 0 or 1
    const int wl  = wid & 7;
    const int b   = ((wl & 3) << 3) + (lane >> 2);    // batch 0..31
    const int ul  = ((wl >> 2) << 2) + (lane & 3);    // local unit 0..7
    const int u   = u0 + ul;
    const int swz = b & 7;
    const int kk0 = khalf * 64;                       // float4-index k range start

    const float* __restrict__ Uw = d ? U_bw : U_fw;
    const float* __restrict__ br = d ? b_rec_bw : b_rec_fw;

    // stage this block's 24 U-columns into SMEM once (k packed into float4)
    for (int idx = tid; idx < 3 * 128 * 8; idx += 512) {
        int g  = idx >> 10;          // /(128*8)
        int kk = (idx >> 3) & 127;
        int uu = idx & 7;
        const float* col = Uw + g * 512 + u0 + uu;
        float4 v;
        v.x = col[(size_t)(4*kk + 0) * U3];
        v.y = col[(size_t)(4*kk + 1) * U3];
        v.z = col[(size_t)(4*kk + 2) * U3];
        v.w = col[(size_t)(4*kk + 3) * U3];
        Us4[idx] = v;
    }

    const float brz = br[0*512 + u];
    const float brr = br[1*512 + u];
    const float brh = br[2*512 + u];

    const float* gx = &g_xproj[0][0][0][0];
    const float4* uzp = Us4 + 0*1024 + ul;
    const float4* urp = Us4 + 1*1024 + ul;
    const float4* uhp = Us4 + 2*1024 + ul;
    const float4* hbp = hs4 + b * 128;

    __syncthreads();

    for (int ts = 0; ts < TT; ts++) {
        const int t   = d ? (TT - 1 - ts) : ts;
        const int buf = ts & 1;

        // stage h_prev into swizzled SMEM (all 512 threads, 8 float4 each)
        const float4* hp_g = (const float4*)&g_h[d][buf][0][0];
#pragma unroll
        for (int i = 0; i < 8; i++) {
            int id = tid + i * 512;        // 0..4095
            int bb = id >> 7;
            int kk = id & 127;
            hs4[bb * 128 + (kk ^ (bb & 7))] = hp_g[id];
        }
        // early global loads for the k-half-0 threads (hidden behind sync + loop)
        float xz = 0.f, xr = 0.f, xh = 0.f;
        int mt = 0;
        if (khalf == 0) {
            size_t xb = ((size_t)d * (BB*TT) + (size_t)b * TT + t) * U3;
            xz = gx[xb + u];
            xr = gx[xb + 512 + u];
            xh = gx[xb + 1024 + u];
            mt = (tokens[b * TT + t] != 0);
        }
        __syncthreads();

        // 256-wide (per k-half) dot products, f32x2, 6 accumulator chains
        unsigned long long az0 = 0ull, az1 = 0ull;
        unsigned long long ar0 = 0ull, ar1 = 0ull;
        unsigned long long ah0 = 0ull, ah1 = 0ull;
#pragma unroll 2
        for (int kk = kk0; kk < kk0 + 64; kk += 2) {
            ulonglong2 hA = *(const ulonglong2*)(hbp + (kk ^ swz));
            ulonglong2 hB = *(const ulonglong2*)(hbp + ((kk + 1) ^ swz));
            ulonglong2 zA = *(const ulonglong2*)(uzp + kk * 8);
            ulonglong2 zB = *(const ulonglong2*)(uzp + (kk + 1) * 8);
            ulonglong2 rA = *(const ulonglong2*)(urp + kk * 8);
            ulonglong2 rB = *(const ulonglong2*)(urp + (kk + 1) * 8);
            ulonglong2 cA = *(const ulonglong2*)(uhp + kk * 8);
            ulonglong2 cB = *(const ulonglong2*)(uhp + (kk + 1) * 8);
            az0 = ffma2(hA.x, zA.x, az0); az1 = ffma2(hA.y, zA.y, az1);
            ar0 = ffma2(hA.x, rA.x, ar0); ar1 = ffma2(hA.y, rA.y, ar1);
            ah0 = ffma2(hA.x, cA.x, ah0); ah1 = ffma2(hA.y, cA.y, ah1);
            az0 = ffma2(hB.x, zB.x, az0); az1 = ffma2(hB.y, zB.y, az1);
            ar0 = ffma2(hB.x, rB.x, ar0); ar1 = ffma2(hB.y, rB.y, ar1);
            ah0 = ffma2(hB.x, cB.x, ah0); ah1 = ffma2(hB.y, cB.y, ah1);
        }
        float2 azf0 = unpack2(az0), azf1 = unpack2(az1);
        float2 arf0 = unpack2(ar0), arf1 = unpack2(ar1);
        float2 ahf0 = unpack2(ah0), ahf1 = unpack2(ah1);
        float hzp = (azf0.x + azf0.y) + (azf1.x + azf1.y);
        float hrp = (arf0.x + arf0.y) + (arf1.x + arf1.y);
        float hhp = (ahf0.x + ahf0.y) + (ahf1.x + ahf1.y);

        // k-half 1 publishes its partials
        if (khalf == 1) {
            float4 v = { hzp, hrp, hhp, 0.f };
            red[b * 8 + ul] = v;
        }
        __syncthreads();

        if (khalf == 0) {
            float4 p = red[b * 8 + ul];
            float hz = hzp + p.x + brz;
            float hr = hrp + p.y + brr;
            float hh = hhp + p.z + brh;

            float z    = 1.f / (1.f + expf(-(xz + hz)));
            float r    = 1.f / (1.f + expf(-(xr + hr)));
            float cand = tanhf(xh + r * hh);
            float hp   = ((const float*)&hbp[(u >> 2) ^ swz])[u & 3];
            float hn   = z * hp + (1.f - z) * cand;
            if (!mt) hn = hp;
            hout[b * 8 + ul] = hn;
        }
        __syncthreads();

        // coalesced writes: 32 rows x 8 floats -> state buffer + output slice
        if (tid < 64) {
            float4 v  = ((const float4*)hout)[tid];
            int row   = tid >> 1;
            int half  = tid & 1;
            *(float4*)&g_h[d][buf ^ 1][row][u0 + half * 4] = v;
            *(float4*)&out[((size_t)row * TT + t) * (2*UU) + (size_t)d * UU + u0 + half * 4] = v;
        }

        // inter-block barrier (per direction, per step); counters pre-zeroed
        if (ts + 1 < TT) {
            __syncthreads();
            if (tid == 0) {
                __threadfence();
                atomicAdd(&g_cnt[d][ts], 1u);
                volatile unsigned* c = &g_cnt[d][ts];
                while (*c < NBLK) { }
                __threadfence();
            }
            __syncthreads();
        }
    }
}

// ---------------- launch ----------------------------------------------------
extern "C" void kernel_launch(void* const* d_in, const int* in_sizes, int n_in,
                              void* d_out, int out_size)
{
    const int*   tokens   = (const int*)  d_in[0];
    const float* emb      = (const float*)d_in[1];
    const float* W_fw     = (const float*)d_in[2];
    const float* U_fw     = (const float*)d_in[3];
    const float* b_in_fw  = (const float*)d_in[4];
    const float* b_rec_fw = (const float*)d_in[5];
    const float* W_bw     = (const float*)d_in[6];
    const float* U_bw     = (const float*)d_in[7];
    const float* b_in_bw  = (const float*)d_in[8];
    const float* b_rec_bw = (const float*)d_in[9];
    float* out = (float*)d_out;

    void* p;
    cudaGetSymbolAddress(&p, g_h);
    cudaMemsetAsync(p, 0, sizeof(g_h));
    cudaGetSymbolAddress(&p, g_cnt);
    cudaMemsetAsync(p, 0, sizeof(g_cnt));

    dim3 gA(U3 / BN, (BB * TT) / BM, 2);
    xproj_kernel<<<gA, 256>>>(tokens, emb, W_fw, b_in_fw, W_bw, b_in_bw);

    cudaFuncSetAttribute(gru_kernel,
                         cudaFuncAttributeMaxDynamicSharedMemorySize, SMEM_BYTES);
    gru_kernel<<<RGRID, 512, SMEM_BYTES>>>(tokens, U_fw, b_rec_fw,
                                           U_bw, b_rec_bw, out);
}

// round 4
// speedup vs baseline: 1.4531x; 1.4325x over previous
#include <cuda_runtime.h>
#include <math.h>
#include <stdint.h>

#define BB 32
#define TT 512
#define EE 256
#define UU 512
#define U3 1536
#define NBLK 64          // blocks per direction in recurrence
#define RGRID (2*NBLK)   // total recurrence blocks

// ---------------- device scratch (static; no runtime allocation) ------------
__device__ float    g_xproj[2][BB][TT][U3];   // ~201 MB: x@W + b_in per direction
__device__ float    g_h[2][2][BB][UU];        // [dir][buf][b][u] double-buffered state
__device__ unsigned g_cnt[2][TT];             // per-step barrier counters (memset to 0 each launch)

// ---------------- packed f32x2 helpers (PTX-only FFMA2 on sm_103a) ----------
__device__ __forceinline__ unsigned long long ffma2(unsigned long long a,
                                                    unsigned long long b,
                                                    unsigned long long c) {
    unsigned long long d;
    asm("fma.rn.f32x2 %0, %1, %2, %3;" : "=l"(d) : "l"(a), "l"(b), "l"(c));
    return d;
}
__device__ __forceinline__ unsigned long long dup2(float x) {
    unsigned long long d;
    asm("mov.b64 %0, {%1, %1};" : "=l"(d) : "f"(x));
    return d;
}
__device__ __forceinline__ float2 unpack2(unsigned long long v) {
    float2 r;
    asm("mov.b64 {%0, %1}, %2;" : "=f"(r.x), "=f"(r.y) : "l"(v));
    return r;
}

// ---------------- Kernel A: x_proj = emb[tokens] @ W + b_in -----------------
#define BM 128
#define BN 64
#define BK 16

__global__ void __launch_bounds__(256) xproj_kernel(
    const int* __restrict__ tokens,
    const float* __restrict__ emb,
    const float* __restrict__ W_fw, const float* __restrict__ b_in_fw,
    const float* __restrict__ W_bw, const float* __restrict__ b_in_bw)
{
    __shared__ __align__(16) float As[BK][BM];
    __shared__ __align__(16) float Bs[BK][BN];
    __shared__ int toks[BM];

    const int d  = blockIdx.z;
    const float* __restrict__ Wp = d ? W_bw : W_fw;
    const float* __restrict__ bp = d ? b_in_bw : b_in_fw;
    const int n0 = blockIdx.x * BN;
    const int m0 = blockIdx.y * BM;
    const int tid = threadIdx.x;
    const int tx = tid & 15;
    const int ty = tid >> 4;

    if (tid < BM) toks[tid] = tokens[m0 + tid];
    __syncthreads();

    unsigned long long acc[4][4];
#pragma unroll
    for (int i = 0; i < 4; i++)
#pragma unroll
        for (int j = 0; j < 4; j++) acc[i][j] = 0ull;

    for (int k0 = 0; k0 < EE; k0 += BK) {
#pragma unroll
        for (int i = 0; i < 2; i++) {
            int id = tid * 2 + i;
            int m  = id >> 2;
            int kg = id & 3;
            float4 v = *(const float4*)(emb + (size_t)toks[m] * EE + k0 + kg * 4);
            As[kg*4+0][m] = v.x; As[kg*4+1][m] = v.y;
            As[kg*4+2][m] = v.z; As[kg*4+3][m] = v.w;
        }
        {
            int k = tid >> 4, ng = tid & 15;
            *(float4*)&Bs[k][ng*4] =
                *(const float4*)(Wp + (size_t)(k0 + k) * U3 + n0 + ng * 4);
        }
        __syncthreads();
#pragma unroll
        for (int k = 0; k < BK; k++) {
            ulonglong2 a01 = *(const ulonglong2*)&As[k][ty*8];
            ulonglong2 a23 = *(const ulonglong2*)&As[k][ty*8+4];
            float4 b4 = *(const float4*)&Bs[k][tx*4];
            unsigned long long ap[4] = {a01.x, a01.y, a23.x, a23.y};
            unsigned long long bp2[4] = {dup2(b4.x), dup2(b4.y), dup2(b4.z), dup2(b4.w)};
#pragma unroll
            for (int i = 0; i < 4; i++)
#pragma unroll
                for (int j = 0; j < 4; j++)
                    acc[i][j] = ffma2(ap[i], bp2[j], acc[i][j]);
        }
        __syncthreads();
    }

    float4 bias = *(const float4*)(bp + n0 + tx * 4);
    float* gx = &g_xproj[0][0][0][0];
#pragma unroll
    for (int i = 0; i < 4; i++) {
        float2 c0 = unpack2(acc[i][0]);
        float2 c1 = unpack2(acc[i][1]);
        float2 c2 = unpack2(acc[i][2]);
        float2 c3 = unpack2(acc[i][3]);
        size_t mlo = (size_t)(m0 + ty * 8 + i * 2);
        float4 vlo = { c0.x + bias.x, c1.x + bias.y, c2.x + bias.z, c3.x + bias.w };
        float4 vhi = { c0.y + bias.x, c1.y + bias.y, c2.y + bias.z, c3.y + bias.w };
        *(float4*)(gx + ((size_t)d * (BB*TT) + mlo)     * U3 + n0 + tx * 4) = vlo;
        *(float4*)(gx + ((size_t)d * (BB*TT) + mlo + 1) * U3 + n0 + tx * 4) = vhi;
    }
}

// ---------------- Kernel B: persistent GRU recurrence -----------------------
// 128 blocks (64/dir), 512 threads, block owns 8 hidden units = 24 GEMM cols.
// Per step: P[32x24] = H[32x512] * Us[512x24], register-tiled:
//   thread = (bgrp 0..7, cgrp 0..3, ks 0..15); tile 4 batches x 6 cols;
//   lane = (bgrp&1)*16 + ks  -> 16-lane-contiguous LDS, U broadcast.
// ksplit reduced with 4-round shfl_xor butterfly (lanes = ks bits).
// SMEM: hs[32][512] + Us[24][512] + hsum[32][25] + hout[32][8]
#define GRU_SMEM_FLOATS (32*512 + 24*512 + 32*25 + 32*8)
#define SMEM_BYTES (GRU_SMEM_FLOATS * 4)

__global__ void __launch_bounds__(512, 1) gru_kernel(
    const int* __restrict__ tokens,
    const float* __restrict__ U_fw, const float* __restrict__ b_rec_fw,
    const float* __restrict__ U_bw, const float* __restrict__ b_rec_bw,
    float* __restrict__ out)
{
    extern __shared__ float smem[];
    float* hs   = smem;                       // [32][512]
    float* Us   = hs + 32*512;                // [24][512], col c = g*8+ul
    float* hsum = Us + 24*512;                // [32][25]
    float* hout = hsum + 32*25;               // [32][8]

    const int bid = blockIdx.x;
    const int d   = bid >> 6;
    const int jb  = bid & (NBLK - 1);
    const int u0  = jb * 8;
    const int tid = threadIdx.x;
    const int wid = tid >> 5;
    const int lane = tid & 31;
    const int bgrp = ((wid >> 2) << 1) + (lane >> 4);   // 0..7
    const int cgrp = wid & 3;                           // 0..3
    const int ks   = lane & 15;                         // 0..15

    const float* __restrict__ Uw = d ? U_bw : U_fw;
    const float* __restrict__ br = d ? b_rec_bw : b_rec_fw;

    // stage this block's 24 U columns: Us[c][k] = Uw[k][g*512 + u0 + ul]
    for (int idx = tid; idx < 24 * 512; idx += 512) {
        int k = idx / 24;
        int c = idx - k * 24;
        int g = c >> 3;
        Us[c * 512 + k] = Uw[(size_t)k * U3 + g * 512 + u0 + (c & 7)];
    }

    // epilogue-thread private constants
    float brz = 0.f, brr = 0.f, brh = 0.f;
    int eb = 0, eu = 0;
    if (tid < 256) {
        eb = tid >> 3; eu = tid & 7;
        brz = br[0*512 + u0 + eu];
        brr = br[1*512 + u0 + eu];
        brh = br[2*512 + u0 + eu];
    }

    const float* gx = &g_xproj[0][0][0][0];
    const unsigned long long* hrow0 = (const unsigned long long*)(hs + (bgrp*4+0)*512);
    const unsigned long long* hrow1 = (const unsigned long long*)(hs + (bgrp*4+1)*512);
    const unsigned long long* hrow2 = (const unsigned long long*)(hs + (bgrp*4+2)*512);
    const unsigned long long* hrow3 = (const unsigned long long*)(hs + (bgrp*4+3)*512);
    const unsigned long long* ucol0 = (const unsigned long long*)(Us + (cgrp*6+0)*512);
    const unsigned long long* ucol1 = (const unsigned long long*)(Us + (cgrp*6+1)*512);
    const unsigned long long* ucol2 = (const unsigned long long*)(Us + (cgrp*6+2)*512);
    const unsigned long long* ucol3 = (const unsigned long long*)(Us + (cgrp*6+3)*512);
    const unsigned long long* ucol4 = (const unsigned long long*)(Us + (cgrp*6+4)*512);
    const unsigned long long* ucol5 = (const unsigned long long*)(Us + (cgrp*6+5)*512);

    __syncthreads();

    for (int ts = 0; ts < TT; ts++) {
        const int t   = d ? (TT - 1 - ts) : ts;
        const int buf = ts & 1;

        // stage h_prev (plain copy, 8 float4 per thread)
        const float4* hp_g = (const float4*)&g_h[d][buf][0][0];
        float4* hs4 = (float4*)hs;
#pragma unroll
        for (int i = 0; i < 8; i++) {
            int id = tid + i * 512;
            hs4[id] = hp_g[id];
        }
        // prefetch epilogue inputs (latency hidden under sync + dot)
        float xz = 0.f, xr = 0.f, xh = 0.f;
        int mt = 0;
        if (tid < 256) {
            size_t xb = ((size_t)d * (BB*TT) + (size_t)eb * TT + t) * U3;
            xz = gx[xb + u0 + eu];
            xr = gx[xb + 512 + u0 + eu];
            xh = gx[xb + 1024 + u0 + eu];
            mt = (tokens[eb * TT + t] != 0);
        }
        __syncthreads();

        // dot: thread tile 4b x 6c over k-chunk (pairs p = ks + 16*i)
        unsigned long long acc[4][6];
#pragma unroll
        for (int i = 0; i < 4; i++)
#pragma unroll
            for (int j = 0; j < 6; j++) acc[i][j] = 0ull;

#pragma unroll 2
        for (int i = 0; i < 16; i++) {
            int p = ks + (i << 4);
            unsigned long long h0 = hrow0[p];
            unsigned long long h1 = hrow1[p];
            unsigned long long h2 = hrow2[p];
            unsigned long long h3 = hrow3[p];
            unsigned long long w0 = ucol0[p];
            unsigned long long w1 = ucol1[p];
            unsigned long long w2 = ucol2[p];
            unsigned long long w3 = ucol3[p];
            unsigned long long w4 = ucol4[p];
            unsigned long long w5 = ucol5[p];
            acc[0][0] = ffma2(h0, w0, acc[0][0]); acc[0][1] = ffma2(h0, w1, acc[0][1]);
            acc[0][2] = ffma2(h0, w2, acc[0][2]); acc[0][3] = ffma2(h0, w3, acc[0][3]);
            acc[0][4] = ffma2(h0, w4, acc[0][4]); acc[0][5] = ffma2(h0, w5, acc[0][5]);
            acc[1][0] = ffma2(h1, w0, acc[1][0]); acc[1][1] = ffma2(h1, w1, acc[1][1]);
            acc[1][2] = ffma2(h1, w2, acc[1][2]); acc[1][3] = ffma2(h1, w3, acc[1][3]);
            acc[1][4] = ffma2(h1, w4, acc[1][4]); acc[1][5] = ffma2(h1, w5, acc[1][5]);
            acc[2][0] = ffma2(h2, w0, acc[2][0]); acc[2][1] = ffma2(h2, w1, acc[2][1]);
            acc[2][2] = ffma2(h2, w2, acc[2][2]); acc[2][3] = ffma2(h2, w3, acc[2][3]);
            acc[2][4] = ffma2(h2, w4, acc[2][4]); acc[2][5] = ffma2(h2, w5, acc[2][5]);
            acc[3][0] = ffma2(h3, w0, acc[3][0]); acc[3][1] = ffma2(h3, w1, acc[3][1]);
            acc[3][2] = ffma2(h3, w2, acc[3][2]); acc[3][3] = ffma2(h3, w3, acc[3][3]);
            acc[3][4] = ffma2(h3, w4, acc[3][4]); acc[3][5] = ffma2(h3, w5, acc[3][5]);
        }

        // horizontal add + butterfly reduce over ks (4 rounds, within 16-lane halves)
        float v[4][6];
#pragma unroll
        for (int i = 0; i < 4; i++)
#pragma unroll
            for (int j = 0; j < 6; j++) {
                float2 p2 = unpack2(acc[i][j]);
                v[i][j] = p2.x + p2.y;
            }
#pragma unroll
        for (int delta = 1; delta <= 8; delta <<= 1)
#pragma unroll
            for (int i = 0; i < 4; i++)
#pragma unroll
                for (int j = 0; j < 6; j++)
                    v[i][j] += __shfl_xor_sync(0xffffffffu, v[i][j], delta);

        if (ks == 0) {
#pragma unroll
            for (int i = 0; i < 4; i++)
#pragma unroll
                for (int j = 0; j < 6; j++)
                    hsum[(bgrp*4 + i) * 25 + cgrp*6 + j] = v[i][j];
        }
        __syncthreads();

        if (tid < 256) {
            float hz = hsum[eb * 25 + 0  + eu] + brz;
            float hr = hsum[eb * 25 + 8  + eu] + brr;
            float hh = hsum[eb * 25 + 16 + eu] + brh;

            float z    = 1.f / (1.f + expf(-(xz + hz)));
            float r    = 1.f / (1.f + expf(-(xr + hr)));
            float cand = tanhf(xh + r * hh);
            float hp   = hs[eb * 512 + u0 + eu];
            float hn   = z * hp + (1.f - z) * cand;
            if (!mt) hn = hp;
            hout[eb * 8 + eu] = hn;
        }
        __syncthreads();

        // coalesced writes: 32 rows x 8 floats -> state buffer + output slice
        if (tid < 64) {
            float4 vv = ((const float4*)hout)[tid];
            int row  = tid >> 1;
            int half = tid & 1;
            *(float4*)&g_h[d][buf ^ 1][row][u0 + half * 4] = vv;
            *(float4*)&out[((size_t)row * TT + t) * (2*UU) + (size_t)d * UU + u0 + half * 4] = vv;
        }

        // inter-block barrier (per direction, per step); counters pre-zeroed
        if (ts + 1 < TT) {
            __syncthreads();
            if (tid == 0) {
                __threadfence();
                atomicAdd(&g_cnt[d][ts], 1u);
                volatile unsigned* c = &g_cnt[d][ts];
                while (*c < NBLK) { }
                __threadfence();
            }
            __syncthreads();
        }
    }
}

// ---------------- launch ----------------------------------------------------
extern "C" void kernel_launch(void* const* d_in, const int* in_sizes, int n_in,
                              void* d_out, int out_size)
{
    const int*   tokens   = (const int*)  d_in[0];
    const float* emb      = (const float*)d_in[1];
    const float* W_fw     = (const float*)d_in[2];
    const float* U_fw     = (const float*)d_in[3];
    const float* b_in_fw  = (const float*)d_in[4];
    const float* b_rec_fw = (const float*)d_in[5];
    const float* W_bw     = (const float*)d_in[6];
    const float* U_bw     = (const float*)d_in[7];
    const float* b_in_bw  = (const float*)d_in[8];
    const float* b_rec_bw = (const float*)d_in[9];
    float* out = (float*)d_out;

    void* p;
    cudaGetSymbolAddress(&p, g_h);
    cudaMemsetAsync(p, 0, sizeof(g_h));
    cudaGetSymbolAddress(&p, g_cnt);
    cudaMemsetAsync(p, 0, sizeof(g_cnt));

    dim3 gA(U3 / BN, (BB * TT) / BM, 2);
    xproj_kernel<<<gA, 256>>>(tokens, emb, W_fw, b_in_fw, W_bw, b_in_bw);

    cudaFuncSetAttribute(gru_kernel,
                         cudaFuncAttributeMaxDynamicSharedMemorySize, SMEM_BYTES);
    gru_kernel<<<RGRID, 512, SMEM_BYTES>>>(tokens, U_fw, b_rec_fw,
                                           U_bw, b_rec_bw, out);
}

// round 5
// speedup vs baseline: 2.0567x; 1.4154x over previous
#include <cuda_runtime.h>
#include <math.h>
#include <stdint.h>

#define BB 32
#define TT 512
#define EE 256
#define UU 512
#define U3 1536
#define NBLK 64          // blocks per direction in recurrence
#define RGRID (2*NBLK)   // total recurrence blocks
#define PADK 516         // padded k-stride (conflict-free fragment LDS)

// ---------------- device scratch (static; no runtime allocation) ------------
__device__ float    g_xproj[2][BB][TT][U3];   // x@W + b_in per direction
__device__ float    g_h[2][2][BB][UU];        // [dir][buf][b][u] double-buffered state
__device__ unsigned g_cnt[2][TT];             // per-step barrier counters (memset to 0)

// ---------------- packed f32x2 helpers (xproj kernel) -----------------------
__device__ __forceinline__ unsigned long long ffma2(unsigned long long a,
                                                    unsigned long long b,
                                                    unsigned long long c) {
    unsigned long long d;
    asm("fma.rn.f32x2 %0, %1, %2, %3;" : "=l"(d) : "l"(a), "l"(b), "l"(c));
    return d;
}
__device__ __forceinline__ unsigned long long dup2(float x) {
    unsigned long long d;
    asm("mov.b64 %0, {%1, %1};" : "=l"(d) : "f"(x));
    return d;
}
__device__ __forceinline__ float2 unpack2(unsigned long long v) {
    float2 r;
    asm("mov.b64 {%0, %1}, %2;" : "=f"(r.x), "=f"(r.y) : "l"(v));
    return r;
}

// ---------------- tf32 mma helper -------------------------------------------
__device__ __forceinline__ void mma_tf32(float& d0, float& d1, float& d2, float& d3,
                                         unsigned a0, unsigned a1, unsigned a2, unsigned a3,
                                         unsigned b0, unsigned b1) {
    asm volatile(
        "mma.sync.aligned.m16n8k8.row.col.f32.tf32.tf32.f32 "
        "{%0,%1,%2,%3}, {%4,%5,%6,%7}, {%8,%9}, {%0,%1,%2,%3};"
        : "+f"(d0), "+f"(d1), "+f"(d2), "+f"(d3)
        : "r"(a0), "r"(a1), "r"(a2), "r"(a3), "r"(b0), "r"(b1));
}
__device__ __forceinline__ unsigned tf32_hi_bits(float x) {
    return __float_as_uint(x) & 0xFFFFE000u;
}

// ---------------- Kernel A: x_proj = emb[tokens] @ W + b_in -----------------
#define BM 128
#define BN 64
#define BK 16

__global__ void __launch_bounds__(256) xproj_kernel(
    const int* __restrict__ tokens,
    const float* __restrict__ emb,
    const float* __restrict__ W_fw, const float* __restrict__ b_in_fw,
    const float* __restrict__ W_bw, const float* __restrict__ b_in_bw)
{
    __shared__ __align__(16) float As[BK][BM];
    __shared__ __align__(16) float Bs[BK][BN];
    __shared__ int toks[BM];

    const int d  = blockIdx.z;
    const float* __restrict__ Wp = d ? W_bw : W_fw;
    const float* __restrict__ bp = d ? b_in_bw : b_in_fw;
    const int n0 = blockIdx.x * BN;
    const int m0 = blockIdx.y * BM;
    const int tid = threadIdx.x;
    const int tx = tid & 15;
    const int ty = tid >> 4;

    if (tid < BM) toks[tid] = tokens[m0 + tid];
    __syncthreads();

    unsigned long long acc[4][4];
#pragma unroll
    for (int i = 0; i < 4; i++)
#pragma unroll
        for (int j = 0; j < 4; j++) acc[i][j] = 0ull;

    for (int k0 = 0; k0 < EE; k0 += BK) {
#pragma unroll
        for (int i = 0; i < 2; i++) {
            int id = tid * 2 + i;
            int m  = id >> 2;
            int kg = id & 3;
            float4 v = *(const float4*)(emb + (size_t)toks[m] * EE + k0 + kg * 4);
            As[kg*4+0][m] = v.x; As[kg*4+1][m] = v.y;
            As[kg*4+2][m] = v.z; As[kg*4+3][m] = v.w;
        }
        {
            int k = tid >> 4, ng = tid & 15;
            *(float4*)&Bs[k][ng*4] =
                *(const float4*)(Wp + (size_t)(k0 + k) * U3 + n0 + ng * 4);
        }
        __syncthreads();
#pragma unroll
        for (int k = 0; k < BK; k++) {
            ulonglong2 a01 = *(const ulonglong2*)&As[k][ty*8];
            ulonglong2 a23 = *(const ulonglong2*)&As[k][ty*8+4];
            float4 b4 = *(const float4*)&Bs[k][tx*4];
            unsigned long long ap[4] = {a01.x, a01.y, a23.x, a23.y};
            unsigned long long bp2[4] = {dup2(b4.x), dup2(b4.y), dup2(b4.z), dup2(b4.w)};
#pragma unroll
            for (int i = 0; i < 4; i++)
#pragma unroll
                for (int j = 0; j < 4; j++)
                    acc[i][j] = ffma2(ap[i], bp2[j], acc[i][j]);
        }
        __syncthreads();
    }

    float4 bias = *(const float4*)(bp + n0 + tx * 4);
    float* gx = &g_xproj[0][0][0][0];
#pragma unroll
    for (int i = 0; i < 4; i++) {
        float2 c0 = unpack2(acc[i][0]);
        float2 c1 = unpack2(acc[i][1]);
        float2 c2 = unpack2(acc[i][2]);
        float2 c3 = unpack2(acc[i][3]);
        size_t mlo = (size_t)(m0 + ty * 8 + i * 2);
        float4 vlo = { c0.x + bias.x, c1.x + bias.y, c2.x + bias.z, c3.x + bias.w };
        float4 vhi = { c0.y + bias.x, c1.y + bias.y, c2.y + bias.z, c3.y + bias.w };
        *(float4*)(gx + ((size_t)d * (BB*TT) + mlo)     * U3 + n0 + tx * 4) = vlo;
        *(float4*)(gx + ((size_t)d * (BB*TT) + mlo + 1) * U3 + n0 + tx * 4) = vhi;
    }
}

// ---------------- Kernel B: persistent GRU recurrence (tf32 tensor cores) ---
// 128 blocks (64/dir), 256 threads = 8 warps. Block owns 8 hidden units
// = 24 GEMM cols. Per step: P[32x24] = H[32x512] * Us[512x24] via
// mma.sync.m16n8k8.tf32 with 2-way split (hi*hi + hi*lo + lo*hi ~ fp32).
// Warp (mi = w&1, kh = w>>1): m-tile 16 rows, k-range 128 (16 k-tiles), n=24.
// U pre-split hi/lo in SMEM (once); h staged fp32, split in-register.
// k-split reduced through 3-slot SMEM psum; epilogue = 256 threads (b,u).
// SMEM floats: hs 32*516 + Ush 24*516 + Usl 24*516 + psum 3*32*24
#define GRU_SMEM_FLOATS (32*PADK + 24*PADK + 24*PADK + 3*32*24)
#define SMEM_BYTES (GRU_SMEM_FLOATS * 4)

__global__ void __launch_bounds__(256, 1) gru_kernel(
    const int* __restrict__ tokens,
    const float* __restrict__ U_fw, const float* __restrict__ b_rec_fw,
    const float* __restrict__ U_bw, const float* __restrict__ b_rec_bw,
    float* __restrict__ out)
{
    extern __shared__ float smem[];
    float* hs   = smem;                        // [32][516]  h (exact fp32)
    float* Ush  = hs + 32*PADK;                // [24][516]  U hi (tf32 bits)
    float* Usl  = Ush + 24*PADK;               // [24][516]  U lo (residual)
    float* psum = Usl + 24*PADK;               // [3][32][24]

    const int bid = blockIdx.x;
    const int d   = bid >> 6;
    const int jb  = bid & (NBLK - 1);
    const int u0  = jb * 8;
    const int tid = threadIdx.x;
    const int wid = tid >> 5;
    const int lane = tid & 31;
    const int mi = wid & 1;          // m-tile (rows mi*16 .. mi*16+15)
    const int kh = wid >> 1;         // k-split 0..3 (k range kh*128 .. +128)
    const int gr = lane >> 2;        // fragment group row
    const int gc = lane & 3;         // fragment group col

    const float* __restrict__ Uw = d ? U_bw : U_fw;
    const float* __restrict__ br = d ? b_rec_bw : b_rec_fw;

    // stage U hi/lo once (reused all 512 steps)
    for (int idx = tid; idx < 24 * 512; idx += 256) {
        int c = idx >> 9;            // col 0..23 (c = g*8 + ul)
        int k = idx & 511;
        int g = c >> 3;
        float v = Uw[(size_t)k * U3 + g * 512 + u0 + (c & 7)];
        unsigned hb = tf32_hi_bits(v);
        float hi = __uint_as_float(hb);
        Ush[c * PADK + k] = hi;
        Usl[c * PADK + k] = v - hi;
    }

    // epilogue mapping (all 256 threads): batch eb, unit eu
    const int eb = tid >> 3, eu = tid & 7;
    const float brz = br[0*512 + u0 + eu];
    const float brr = br[1*512 + u0 + eu];
    const float brh = br[2*512 + u0 + eu];

    const float* gx = &g_xproj[0][0][0][0];

    // fragment base offsets
    const int rA0 = (mi*16 + gr) * PADK + gc;          // A row frag (rows gr / gr+8)
    const int rA1 = rA0 + 8 * PADK;
    const int cB  = gr * PADK + gc;                    // B frag within n-tile block

    __syncthreads();

    for (int ts = 0; ts < TT; ts++) {
        const int t   = d ? (TT - 1 - ts) : ts;
        const int buf = ts & 1;

        // stage h_prev fp32 into padded SMEM rows
        const float4* hp_g = (const float4*)&g_h[d][buf][0][0];
#pragma unroll
        for (int i = 0; i < 16; i++) {
            int id  = tid + i * 256;       // 0..4095 float4 slots
            int row = id >> 7;
            int q   = id & 127;
            *(float4*)&hs[row * PADK + q * 4] = hp_g[id];
        }
        // prefetch epilogue inputs
        size_t xb = ((size_t)d * (BB*TT) + (size_t)eb * TT + t) * U3;
        float xz = gx[xb + u0 + eu];
        float xr = gx[xb + 512 + u0 + eu];
        float xh = gx[xb + 1024 + u0 + eu];
        int   mt = (tokens[eb * TT + t] != 0);
        __syncthreads();

        // ---- tensor-core dot: 16 k-tiles, 3 n-tiles, split products ----
        float D[3][4];
#pragma unroll
        for (int j = 0; j < 3; j++)
#pragma unroll
            for (int q = 0; q < 4; q++) D[j][q] = 0.f;

        const int kbase = kh * 128;
#pragma unroll 4
        for (int kt = 0; kt < 16; kt++) {
            int k0 = kbase + kt * 8;
            float f0 = hs[rA0 + k0];
            float f1 = hs[rA1 + k0];
            float f2 = hs[rA0 + k0 + 4];
            float f3 = hs[rA1 + k0 + 4];
            unsigned a0h = tf32_hi_bits(f0);
            unsigned a1h = tf32_hi_bits(f1);
            unsigned a2h = tf32_hi_bits(f2);
            unsigned a3h = tf32_hi_bits(f3);
            unsigned a0l = __float_as_uint(f0 - __uint_as_float(a0h));
            unsigned a1l = __float_as_uint(f1 - __uint_as_float(a1h));
            unsigned a2l = __float_as_uint(f2 - __uint_as_float(a2h));
            unsigned a3l = __float_as_uint(f3 - __uint_as_float(a3h));
#pragma unroll
            for (int j = 0; j < 3; j++) {
                const float* bh = Ush + (j*8) * PADK + cB + k0;
                const float* bl = Usl + (j*8) * PADK + cB + k0;
                unsigned b0 = __float_as_uint(bh[0]);
                unsigned b1 = __float_as_uint(bh[4]);
                unsigned c0 = __float_as_uint(bl[0]);
                unsigned c1 = __float_as_uint(bl[4]);
                mma_tf32(D[j][0], D[j][1], D[j][2], D[j][3],
                         a0h, a1h, a2h, a3h, b0, b1);      // hi*hi
                mma_tf32(D[j][0], D[j][1], D[j][2], D[j][3],
                         a0h, a1h, a2h, a3h, c0, c1);      // hi*lo
                mma_tf32(D[j][0], D[j][1], D[j][2], D[j][3],
                         a0l, a1l, a2l, a3l, b0, b1);      // lo*hi
            }
        }

        // ---- k-split reduction through psum ----
        const int r0 = mi*16 + gr;
        const int r1 = r0 + 8;
        if (kh > 0) {
#pragma unroll
            for (int j = 0; j < 3; j++) {
                int cc = j*8 + gc*2;
                *(float2*)&psum[((kh-1)*32 + r0)*24 + cc] = make_float2(D[j][0], D[j][1]);
                *(float2*)&psum[((kh-1)*32 + r1)*24 + cc] = make_float2(D[j][2], D[j][3]);
            }
        }
        __syncthreads();
        if (kh == 0) {
#pragma unroll
            for (int s = 0; s < 3; s++)
#pragma unroll
                for (int j = 0; j < 3; j++) {
                    int cc = j*8 + gc*2;
                    float2 p0 = *(const float2*)&psum[(s*32 + r0)*24 + cc];
                    float2 p1 = *(const float2*)&psum[(s*32 + r1)*24 + cc];
                    D[j][0] += p0.x; D[j][1] += p0.y;
                    D[j][2] += p1.x; D[j][3] += p1.y;
                }
#pragma unroll
            for (int j = 0; j < 3; j++) {
                int cc = j*8 + gc*2;
                *(float2*)&psum[r0*24 + cc] = make_float2(D[j][0], D[j][1]);
                *(float2*)&psum[r1*24 + cc] = make_float2(D[j][2], D[j][3]);
            }
        }
        __syncthreads();

        // ---- epilogue: each thread = one (batch, unit) ----
        {
            float hz = psum[eb*24 + 0  + eu] + brz;
            float hr = psum[eb*24 + 8  + eu] + brr;
            float hh = psum[eb*24 + 16 + eu] + brh;

            float z    = 1.f / (1.f + expf(-(xz + hz)));
            float r    = 1.f / (1.f + expf(-(xr + hr)));
            float cand = tanhf(xh + r * hh);
            float hp   = hs[eb * PADK + u0 + eu];
            float hn   = z * hp + (1.f - z) * cand;
            if (!mt) hn = hp;

            g_h[d][buf ^ 1][eb][u0 + eu] = hn;
            out[((size_t)eb * TT + t) * (2*UU) + (size_t)d * UU + u0 + eu] = hn;
        }

        // inter-block barrier (per direction, per step); counters pre-zeroed
        if (ts + 1 < TT) {
            __syncthreads();
            if (tid == 0) {
                __threadfence();
                atomicAdd(&g_cnt[d][ts], 1u);
                volatile unsigned* c = &g_cnt[d][ts];
                while (*c < NBLK) { }
                __threadfence();
            }
            __syncthreads();
        }
    }
}

// ---------------- launch ----------------------------------------------------
extern "C" void kernel_launch(void* const* d_in, const int* in_sizes, int n_in,
                              void* d_out, int out_size)
{
    const int*   tokens   = (const int*)  d_in[0];
    const float* emb      = (const float*)d_in[1];
    const float* W_fw     = (const float*)d_in[2];
    const float* U_fw     = (const float*)d_in[3];
    const float* b_in_fw  = (const float*)d_in[4];
    const float* b_rec_fw = (const float*)d_in[5];
    const float* W_bw     = (const float*)d_in[6];
    const float* U_bw     = (const float*)d_in[7];
    const float* b_in_bw  = (const float*)d_in[8];
    const float* b_rec_bw = (const float*)d_in[9];
    float* out = (float*)d_out;

    void* p;
    cudaGetSymbolAddress(&p, g_h);
    cudaMemsetAsync(p, 0, sizeof(g_h));
    cudaGetSymbolAddress(&p, g_cnt);
    cudaMemsetAsync(p, 0, sizeof(g_cnt));

    dim3 gA(U3 / BN, (BB * TT) / BM, 2);
    xproj_kernel<<<gA, 256>>>(tokens, emb, W_fw, b_in_fw, W_bw, b_in_bw);

    cudaFuncSetAttribute(gru_kernel,
                         cudaFuncAttributeMaxDynamicSharedMemorySize, SMEM_BYTES);
    gru_kernel<<<RGRID, 256, SMEM_BYTES>>>(tokens, U_fw, b_rec_fw,
                                           U_bw, b_rec_bw, out);
}